// round 2
// baseline (speedup 1.0000x reference)
#include <cuda_runtime.h>
#include <cstdint>
#include <math.h>

#define BDIM 128

static constexpr int Bb  = 64;
static constexpr int Hh  = 8;
static constexpr int Mm  = 1024;
static constexpr int Cc  = 128;
static constexpr int MID = 64;
static constexpr int TM  = 32;    // m rows per smem tile
static constexpr int XS  = 132;   // padded row stride (conflict-free: 132%32==4)

__device__ __forceinline__ float to_tf32(float x){
    uint32_t r;
    asm("cvt.rna.tf32.f32 %0, %1;" : "=r"(r) : "f"(x));
    return __uint_as_float(r);
}

__device__ __forceinline__ void mma8(float d[4],
    uint32_t a0, uint32_t a1, uint32_t a2, uint32_t a3,
    uint32_t b0, uint32_t b1)
{
    asm volatile(
        "mma.sync.aligned.m16n8k8.row.col.f32.tf32.tf32.f32 "
        "{%0,%1,%2,%3}, {%4,%5,%6,%7}, {%8,%9}, {%0,%1,%2,%3};"
        : "+f"(d[0]), "+f"(d[1]), "+f"(d[2]), "+f"(d[3])
        : "r"(a0), "r"(a1), "r"(a2), "r"(a3), "r"(b0), "r"(b1));
}

__global__ __launch_bounds__(BDIM)
void scatt_kernel(
    const float* __restrict__ query,
    const float* __restrict__ key_feat,
    const int*   __restrict__ att_mask,
    const float* __restrict__ value1,
    const float* __restrict__ value2,
    const float* __restrict__ w_basic,
    const float* __restrict__ b_basic,
    const float* __restrict__ w_last,
    const float* __restrict__ w_last2,
    const float* __restrict__ b_last2,
    float*       __restrict__ out)
{
    const int bh = blockIdx.x;
    const int b  = bh / Hh;
    const int h  = bh % Hh;
    const int tid = threadIdx.x;
    const int w   = tid >> 5;
    const int l   = tid & 31;
    const int g   = l >> 2;     // groupID (0..7)
    const int tig = l & 3;      // thread-in-group (0..3)

    __shared__ __align__(16) float xs[TM][XS];      // x tile (tf32 bits)
    __shared__ float s_lp[4][Mm];                   // per-warp logit partials
    __shared__ int   s_idx[Mm];                     // compacted row indices
    __shared__ float s_pool[MID];
    __shared__ __align__(16) float s_v2[4][Cc];
    __shared__ float s_alpha[Cc];
    __shared__ float s_red[8];
    __shared__ int   s_cnt;

    // ---- 1. Compact unmasked rows (warp 0, ballot prefix) ----
    if (w == 0){
        int base = 0;
        const int* mp = att_mask + b * Mm;
        for (int c = 0; c < Mm; c += 32){
            int mk = mp[c + l];
            unsigned bal = __ballot_sync(0xffffffffu, mk != 0);
            if (mk) s_idx[base + __popc(bal & ((1u << l) - 1u))] = c + l;
            base += __popc(bal);
        }
        if (l == 0) s_cnt = base;
    }
    __syncthreads();
    const int Mc    = s_cnt;
    const int McPad = (Mc + TM - 1) & ~(TM - 1);
    for (int j = Mc + tid; j < McPad; j += BDIM) s_idx[j] = 0;  // pad (validity-guarded later)

    // ---- 2. Preload W fragments (tf32), bias, w_last, q ----
    uint32_t wb0[16][2], wb1[16][2];
    const float* wbp = w_basic + (size_t)h * Cc * MID;
    const int nb0 = 16 * w, nb1 = 16 * w + 8;
    #pragma unroll
    for (int k = 0; k < 16; k++){
        int r0 = 8 * k + tig, r1 = r0 + 4;
        wb0[k][0] = __float_as_uint(to_tf32(wbp[r0 * MID + nb0 + g]));
        wb0[k][1] = __float_as_uint(to_tf32(wbp[r1 * MID + nb0 + g]));
        wb1[k][0] = __float_as_uint(to_tf32(wbp[r0 * MID + nb1 + g]));
        wb1[k][1] = __float_as_uint(to_tf32(wbp[r1 * MID + nb1 + g]));
    }
    const int c0 = nb0 + 2 * tig, c2 = nb1 + 2 * tig;
    float bb[4], wl[4];
    bb[0] = b_basic[h * MID + c0];     bb[1] = b_basic[h * MID + c0 + 1];
    bb[2] = b_basic[h * MID + c2];     bb[3] = b_basic[h * MID + c2 + 1];
    wl[0] = w_last[h * MID + c0];      wl[1] = w_last[h * MID + c0 + 1];
    wl[2] = w_last[h * MID + c2];      wl[3] = w_last[h * MID + c2 + 1];
    float4 q4 = *((const float4*)(query + (size_t)bh * Cc) + l);

    const float* kf = key_feat + (size_t)bh * Mm * Cc;
    float pa[4] = {0.f, 0.f, 0.f, 0.f};
    const int NT = McPad / TM;

    __syncthreads();   // s_idx padding visible to all

    // ---- 3. Main GEMM loop over compacted m-tiles ----
    float4 pf[8];
    // prefetch + stage tile 0
    if (NT > 0){
        #pragma unroll
        for (int r = 0; r < 8; r++){
            int row = s_idx[w + 4 * r];
            pf[r] = *((const float4*)(kf + (size_t)row * Cc) + l);
        }
        #pragma unroll
        for (int r = 0; r < 8; r++){
            int mloc = w + 4 * r;
            float4 v = pf[r];
            v.x = to_tf32(v.x * q4.x); v.y = to_tf32(v.y * q4.y);
            v.z = to_tf32(v.z * q4.z); v.w = to_tf32(v.w * q4.w);
            *((float4*)&xs[mloc][4 * l]) = v;
        }
    }
    __syncthreads();

    for (int t = 0; t < NT; t++){
        // prefetch next tile into registers (overlaps with MMA below)
        if (t + 1 < NT){
            #pragma unroll
            for (int r = 0; r < 8; r++){
                int row = s_idx[(t + 1) * TM + w + 4 * r];
                pf[r] = *((const float4*)(kf + (size_t)row * Cc) + l);
            }
        }
        #pragma unroll
        for (int sub = 0; sub < 2; sub++){
            float d0[4] = {0.f,0.f,0.f,0.f};
            float d1[4] = {0.f,0.f,0.f,0.f};
            const float* ab = &xs[16 * sub + g][tig];
            #pragma unroll
            for (int k = 0; k < 16; k++){
                uint32_t a0 = __float_as_uint(ab[8 * k]);
                uint32_t a1 = __float_as_uint(ab[8 * XS + 8 * k]);
                uint32_t a2 = __float_as_uint(ab[8 * k + 4]);
                uint32_t a3 = __float_as_uint(ab[8 * XS + 8 * k + 4]);
                mma8(d0, a0, a1, a2, a3, wb0[k][0], wb0[k][1]);
                mma8(d1, a0, a1, a2, a3, wb1[k][0], wb1[k][1]);
            }
            // epilogue: bias+relu, pool partials, logit partials
            int m0 = t * TM + 16 * sub;
            float vg  = (m0 + g)     < Mc ? 1.f : 0.f;
            float vg8 = (m0 + g + 8) < Mc ? 1.f : 0.f;
            float rA0 = fmaxf(d0[0] + bb[0], 0.f), rA1 = fmaxf(d0[1] + bb[1], 0.f);
            float rA2 = fmaxf(d0[2] + bb[0], 0.f), rA3 = fmaxf(d0[3] + bb[1], 0.f);
            float rB0 = fmaxf(d1[0] + bb[2], 0.f), rB1 = fmaxf(d1[1] + bb[3], 0.f);
            float rB2 = fmaxf(d1[2] + bb[2], 0.f), rB3 = fmaxf(d1[3] + bb[3], 0.f);
            pa[0] += vg * rA0 + vg8 * rA2;
            pa[1] += vg * rA1 + vg8 * rA3;
            pa[2] += vg * rB0 + vg8 * rB2;
            pa[3] += vg * rB1 + vg8 * rB3;
            float lg  = rA0 * wl[0] + rA1 * wl[1] + rB0 * wl[2] + rB1 * wl[3];
            float lg8 = rA2 * wl[0] + rA3 * wl[1] + rB2 * wl[2] + rB3 * wl[3];
            lg  += __shfl_xor_sync(0xffffffffu, lg,  1);
            lg  += __shfl_xor_sync(0xffffffffu, lg,  2);
            lg8 += __shfl_xor_sync(0xffffffffu, lg8, 1);
            lg8 += __shfl_xor_sync(0xffffffffu, lg8, 2);
            if (tig == 0){
                s_lp[w][m0 + g]     = lg;
                s_lp[w][m0 + g + 8] = lg8;
            }
        }
        __syncthreads();
        if (t + 1 < NT){
            #pragma unroll
            for (int r = 0; r < 8; r++){
                int mloc = w + 4 * r;
                float4 v = pf[r];
                v.x = to_tf32(v.x * q4.x); v.y = to_tf32(v.y * q4.y);
                v.z = to_tf32(v.z * q4.z); v.w = to_tf32(v.w * q4.w);
                *((float4*)&xs[mloc][4 * l]) = v;
            }
        }
        __syncthreads();
    }

    // ---- 4. Pool: reduce over g within warp, store (deterministic, no atomics) ----
    #pragma unroll
    for (int c = 0; c < 4; c++){
        pa[c] += __shfl_xor_sync(0xffffffffu, pa[c], 4);
        pa[c] += __shfl_xor_sync(0xffffffffu, pa[c], 8);
        pa[c] += __shfl_xor_sync(0xffffffffu, pa[c], 16);
    }
    if (l < 4){  // lanes with g==0, tig==l
        s_pool[c0]     = pa[0];
        s_pool[c0 + 1] = pa[1];
        s_pool[c2]     = pa[2];
        s_pool[c2 + 1] = pa[3];
    }
    __syncthreads();

    // ---- 5. Softmax over compacted logits ----
    float lmax = -3.0e38f;
    for (int j = tid; j < Mc; j += BDIM){
        float lv = s_lp[0][j] + s_lp[1][j] + s_lp[2][j] + s_lp[3][j];
        s_lp[0][j] = lv;
        lmax = fmaxf(lmax, lv);
    }
    #pragma unroll
    for (int off = 16; off; off >>= 1)
        lmax = fmaxf(lmax, __shfl_xor_sync(0xffffffffu, lmax, off));
    if (l == 0) s_red[w] = lmax;
    __syncthreads();
    lmax = fmaxf(fmaxf(s_red[0], s_red[1]), fmaxf(s_red[2], s_red[3]));

    float lsum = 0.f;
    for (int j = tid; j < Mc; j += BDIM){
        float e = expf(s_lp[0][j] - lmax);
        s_lp[0][j] = e;
        lsum += e;
    }
    #pragma unroll
    for (int off = 16; off; off >>= 1)
        lsum += __shfl_xor_sync(0xffffffffu, lsum, off);
    if (l == 0) s_red[4 + w] = lsum;
    __syncthreads();
    lsum = s_red[4] + s_red[5] + s_red[6] + s_red[7];

    // ---- 6. alpha_channel = sigmoid(poolmean @ w_last2 + b_last2) ----
    {
        float acc = 0.f;
        const float* w2 = w_last2 + (size_t)h * MID * Cc + tid;
        #pragma unroll 8
        for (int o = 0; o < MID; o++) acc += s_pool[o] * w2[o * Cc];
        float ac = acc / (float)Mc + b_last2[h * Cc + tid];
        s_alpha[tid] = 1.f / (1.f + expf(-ac));
    }

    // ---- 7. v2 = sum_j p[j] * value2[row_j, :]  (gathered, masked rows skipped) ----
    const float* v2p = value2 + (size_t)bh * Mm * Cc;
    float4 acc = make_float4(0.f, 0.f, 0.f, 0.f);
    for (int j = w; j < Mc; j += 4){
        float p  = s_lp[0][j];
        int row  = s_idx[j];
        float4 v = *((const float4*)(v2p + (size_t)row * Cc) + l);
        acc.x += p * v.x; acc.y += p * v.y;
        acc.z += p * v.z; acc.w += p * v.w;
    }
    *((float4*)&s_v2[w][4 * l]) = acc;
    __syncthreads();

    // ---- 8. Final output ----
    {
        float invs = 1.f / lsum;
        float v2v  = (s_v2[0][tid] + s_v2[1][tid] + s_v2[2][tid] + s_v2[3][tid]) * invs;
        out[(size_t)bh * Cc + tid] =
            value1[(size_t)bh * Cc + tid] * v2v * s_alpha[tid];
    }
}

extern "C" void kernel_launch(void* const* d_in, const int* in_sizes, int n_in,
                              void* d_out, int out_size)
{
    (void)in_sizes; (void)n_in; (void)out_size;
    const float* query    = (const float*)d_in[0];
    const float* key_feat = (const float*)d_in[1];
    const int*   att_mask = (const int*)  d_in[2];
    const float* value1   = (const float*)d_in[3];
    const float* value2   = (const float*)d_in[4];
    const float* w_basic  = (const float*)d_in[5];
    const float* b_basic  = (const float*)d_in[6];
    const float* w_last   = (const float*)d_in[7];
    // d_in[8] = b_last: uniform logit shift, cancels in softmax — unused.
    const float* w_last2  = (const float*)d_in[9];
    const float* b_last2  = (const float*)d_in[10];
    float* out = (float*)d_out;

    scatt_kernel<<<Bb * Hh, BDIM>>>(query, key_feat, att_mask, value1, value2,
                                    w_basic, b_basic, w_last, w_last2, b_last2, out);
}